// round 9
// baseline (speedup 1.0000x reference)
#include <cuda_runtime.h>
#include <cuda_fp16.h>

#define NLINKS 10000
#define NPATHS 100000
#define PLEN 8
#define NE (NPATHS*PLEN)
#define HD 32
#define G3 96
#define TROUNDS 8
#define SROW 49   // smem gi row stride in u32 (odd -> conflict-free)

typedef unsigned long long u64;

// ---------------- scratch (device globals; no allocation allowed) ----------------
__device__ __align__(16) __half g_msgs[NE*HD];         // 51.2 MB, link-sorted hop messages (fp16)
__device__ __align__(16) float g_link_state[NLINKS*HD];
__device__ __align__(16) float g_path_state[NPATHS*HD];
__device__ __align__(16) __half g_giH[NLINKS*G3];      // per-round gi per link, fp16 (48 u32/row)
__device__ int g_counts[NLINKS];      // invariant: ==0 on kernel_launch entry (BSS init; k_linkgi restores)
__device__ int g_offsets[NLINKS+1];
__device__ int g_pos[NE];

// ---------------- helpers ----------------
__device__ __forceinline__ float fsig(float x){ return __fdividef(1.f, 1.f + __expf(-x)); }
__device__ __forceinline__ float ftanh(float x){ return __fdividef(2.f, 1.f + __expf(-2.f*x)) - 1.f; }

__device__ __forceinline__ void fma2(u64 &acc, u64 a, u64 b){
    asm("fma.rn.f32x2 %0, %1, %2, %0;" : "+l"(acc) : "l"(a), "l"(b));
}
__device__ __forceinline__ float lo2(u64 v){ return __uint_as_float((unsigned)v); }
__device__ __forceinline__ float hi2(u64 v){ return __uint_as_float((unsigned)(v>>32)); }
__device__ __forceinline__ u64 pk2(float a, float b){
    u64 r; asm("mov.b64 %0, {%1, %2};" : "=l"(r) : "f"(a), "f"(b)); return r;
}

// full GRU gate epilogue for a packed j-pair
__device__ __forceinline__ u64 gatepair(
    u64 aR0,u64 aR1,u64 aZ0,u64 aZ1,u64 aN0,u64 aN1,
    float br0,float br1,float bz0,float bz1,float bn0,float bn1,
    float gr0,float gr1,float gz0,float gz1,float gn0,float gn1,
    u64 hold)
{
    float ghr0 = lo2(aR0)+hi2(aR0)+br0;
    float ghr1 = lo2(aR1)+hi2(aR1)+br1;
    float ghz0 = lo2(aZ0)+hi2(aZ0)+bz0;
    float ghz1 = lo2(aZ1)+hi2(aZ1)+bz1;
    float ghn0 = lo2(aN0)+hi2(aN0)+bn0;
    float ghn1 = lo2(aN1)+hi2(aN1)+bn1;
    float r0 = fsig(gr0 + ghr0), r1 = fsig(gr1 + ghr1);
    float z0 = fsig(gz0 + ghz0), z1 = fsig(gz1 + ghz1);
    float n0 = ftanh(gn0 + r0*ghn0), n1 = ftanh(gn1 + r1*ghn1);
    float h0 = lo2(hold), h1 = hi2(hold);
    return pk2(n0 + z0*(h0 - n0), n1 + z1*(h1 - n1));
}

// ---------------- setup: counting sort of links -> CSR ----------------
__global__ void k_hist(const int* __restrict__ links){
    int e = blockIdx.x*blockDim.x + threadIdx.x;
    if (e < NE) atomicAdd(&g_counts[links[e]], 1);
}
__global__ void k_scan(){
    __shared__ int ssum[256];
    const int CH = (NLINKS + 255) / 256;   // 40
    int t = threadIdx.x;
    int base = t*CH;
    int s = 0;
    for (int i = 0; i < CH; i++){ int x = base+i; if (x < NLINKS) s += g_counts[x]; }
    ssum[t] = s;
    __syncthreads();
    if (t == 0){
        int run = 0;
        for (int i = 0; i < 256; i++){ int v = ssum[i]; ssum[i] = run; run += v; }
        g_offsets[NLINKS] = run;
    }
    __syncthreads();
    int run = ssum[t];
    for (int i = 0; i < CH; i++){
        int x = base+i;
        if (x < NLINKS){ g_offsets[x] = run; run += g_counts[x]; g_counts[x] = 0; }
    }
}
__global__ void k_pos(const int* __restrict__ links){
    int e = blockIdx.x*blockDim.x + threadIdx.x;
    if (e < NE){
        int l = links[e];
        g_pos[e] = g_offsets[l] + atomicAdd(&g_counts[l], 1);
    }
}

// ---------------- path GRU: 8 steps, M=2 paths/thread, f32x2 FMAs ----------------
// FIRST: round 0 — h init = [bw,0..], gi inline from cap (no g_gi read/staging).
// WRITE: write per-hop messages (skipped last round).
template<bool FIRST, bool WRITE>
__global__ void __launch_bounds__(64) k_path(const int* __restrict__ links,
        const float* __restrict__ pWhh, const float* __restrict__ pbhh,
        const float* __restrict__ pWih, const float* __restrict__ pbih,
        const float* __restrict__ cap, const float* __restrict__ bw)
{
    __shared__ __align__(16) float sW[G3*HD];   // Whh row-major [96][32]
    __shared__ float sb[G3];                    // bhh
    __shared__ float sW0[G3], sB0[G3];          // round-0 inline gi: Wih col0 + bih
    __shared__ unsigned sGiU[2][64*SROW];       // fp16 staged gi rows (48 u32 payload, stride 49)

    for (int i = threadIdx.x; i < G3*HD; i += 64) sW[i] = pWhh[i];
    for (int i = threadIdx.x; i < G3;    i += 64){
        sb[i] = pbhh[i];
        if (FIRST){ sW0[i] = pWih[i*HD]; sB0[i] = pbih[i]; }
    }
    __syncthreads();

    const int w = threadIdx.x >> 5, lane = threadIdx.x & 31;
    const int wg = blockIdx.x*2 + w;            // 64 paths per warp-group
    const int NWG = (NPATHS + 63)/64;           // 1563
    if (wg >= NWG) return;                      // warp-uniform
    const int pA = wg*64 + lane;
    const bool hasB = (wg*64 + 63 < NPATHS);    // warp-uniform; last wg has A only
    const int pB = pA + 32;

    u64 h2A[16], h2B[16], h2nA[16], h2nB[16];
    if (FIRST){
        h2A[0] = pk2(__ldg(bw + pA), 0.f);
        h2B[0] = hasB ? pk2(__ldg(bw + pB), 0.f) : 0ull;
        #pragma unroll
        for (int i = 1; i < 16; i++){ h2A[i] = 0ull; h2B[i] = 0ull; }
    } else {
        const float4* hp = (const float4*)(g_path_state + (size_t)pA*HD);
        #pragma unroll
        for (int i = 0; i < 8; i++){
            float4 v = hp[i];
            h2A[2*i] = pk2(v.x, v.y); h2A[2*i+1] = pk2(v.z, v.w);
        }
        if (hasB){
            const float4* hq = (const float4*)(g_path_state + (size_t)pB*HD);
            #pragma unroll
            for (int i = 0; i < 8; i++){
                float4 v = hq[i];
                h2B[2*i] = pk2(v.x, v.y); h2B[2*i+1] = pk2(v.z, v.w);
            }
        } else {
            #pragma unroll
            for (int i = 0; i < 16; i++) h2B[i] = 0ull;
        }
    }

    unsigned* myGiU = &sGiU[w][0];
    const __half2* gA = (const __half2*)(myGiU + lane*SROW);
    const __half2* gB = (const __half2*)(myGiU + (32 + lane)*SROW);

    #pragma unroll 1
    for (int s = 0; s < PLEN; s++){
        int lnkA = __ldg(links + pA*PLEN + s);
        int lnkB = hasB ? __ldg(links + pB*PLEN + s) : 0;
        float capA = 0.f, capB = 0.f;
        if (FIRST){
            capA = __ldg(cap + lnkA);
            capB = hasB ? __ldg(cap + lnkB) : 0.f;
        } else {
            // stage 64 gi rows (48 u32 of fp16 each), coalesced
            const unsigned* gbase = (const unsigned*)g_giH;
            #pragma unroll
            for (int r = 0; r < 32; r++){
                int lr = __shfl_sync(0xffffffffu, lnkA, r);
                const unsigned* g = gbase + lr*48;
                unsigned* dst = myGiU + r*SROW;
                dst[lane] = g[lane];
                if (lane < 16) dst[32 + lane] = g[32 + lane];
            }
            if (hasB){
                #pragma unroll
                for (int r = 0; r < 32; r++){
                    int lr = __shfl_sync(0xffffffffu, lnkB, r);
                    const unsigned* g = gbase + lr*48;
                    unsigned* dst = myGiU + (32 + r)*SROW;
                    dst[lane] = g[lane];
                    if (lane < 16) dst[32 + lane] = g[32 + lane];
                }
            }
            __syncwarp();
        }

        #pragma unroll
        for (int j2 = 0; j2 < 16; j2++){
            const int j0 = 2*j2, j1 = j0 + 1;
            u64 aR0=0ull,aR1=0ull,aZ0=0ull,aZ1=0ull,aN0=0ull,aN1=0ull;
            u64 cR0=0ull,cR1=0ull,cZ0=0ull,cZ1=0ull,cN0=0ull,cN1=0ull;
            const ulonglong2* wR0 = (const ulonglong2*)(sW + j0*HD);
            const ulonglong2* wR1 = (const ulonglong2*)(sW + j1*HD);
            const ulonglong2* wZ0 = (const ulonglong2*)(sW + (32+j0)*HD);
            const ulonglong2* wZ1 = (const ulonglong2*)(sW + (32+j1)*HD);
            const ulonglong2* wN0 = (const ulonglong2*)(sW + (64+j0)*HD);
            const ulonglong2* wN1 = (const ulonglong2*)(sW + (64+j1)*HD);
            #pragma unroll
            for (int k = 0; k < 8; k++){
                ulonglong2 a = wR0[k], b = wR1[k], c = wZ0[k];
                ulonglong2 d = wZ1[k], e = wN0[k], f = wN1[k];
                u64 ha = h2A[2*k], hb = h2A[2*k+1];
                fma2(aR0, ha, a.x); fma2(aR0, hb, a.y);
                fma2(aR1, ha, b.x); fma2(aR1, hb, b.y);
                fma2(aZ0, ha, c.x); fma2(aZ0, hb, c.y);
                fma2(aZ1, ha, d.x); fma2(aZ1, hb, d.y);
                fma2(aN0, ha, e.x); fma2(aN0, hb, e.y);
                fma2(aN1, ha, f.x); fma2(aN1, hb, f.y);
                u64 ga = h2B[2*k], gb = h2B[2*k+1];
                fma2(cR0, ga, a.x); fma2(cR0, gb, a.y);
                fma2(cR1, ga, b.x); fma2(cR1, gb, b.y);
                fma2(cZ0, ga, c.x); fma2(cZ0, gb, c.y);
                fma2(cZ1, ga, d.x); fma2(cZ1, gb, d.y);
                fma2(cN0, ga, e.x); fma2(cN0, gb, e.y);
                fma2(cN1, ga, f.x); fma2(cN1, gb, f.y);
            }
            float br0 = sb[j0], br1 = sb[j1];
            float bz0 = sb[32+j0], bz1 = sb[32+j1];
            float bn0 = sb[64+j0], bn1 = sb[64+j1];
            float grA0, grA1, gzA0, gzA1, gnA0, gnA1;
            float grB0, grB1, gzB0, gzB1, gnB0, gnB1;
            if (FIRST){
                grA0 = __fmaf_rn(capA, sW0[j0], sB0[j0]);
                grA1 = __fmaf_rn(capA, sW0[j1], sB0[j1]);
                gzA0 = __fmaf_rn(capA, sW0[32+j0], sB0[32+j0]);
                gzA1 = __fmaf_rn(capA, sW0[32+j1], sB0[32+j1]);
                gnA0 = __fmaf_rn(capA, sW0[64+j0], sB0[64+j0]);
                gnA1 = __fmaf_rn(capA, sW0[64+j1], sB0[64+j1]);
                grB0 = __fmaf_rn(capB, sW0[j0], sB0[j0]);
                grB1 = __fmaf_rn(capB, sW0[j1], sB0[j1]);
                gzB0 = __fmaf_rn(capB, sW0[32+j0], sB0[32+j0]);
                gzB1 = __fmaf_rn(capB, sW0[32+j1], sB0[32+j1]);
                gnB0 = __fmaf_rn(capB, sW0[64+j0], sB0[64+j0]);
                gnB1 = __fmaf_rn(capB, sW0[64+j1], sB0[64+j1]);
            } else {
                float2 r = __half22float2(gA[j2]);
                float2 z = __half22float2(gA[16 + j2]);
                float2 n = __half22float2(gA[32 + j2]);
                grA0 = r.x; grA1 = r.y; gzA0 = z.x; gzA1 = z.y; gnA0 = n.x; gnA1 = n.y;
                float2 rb = __half22float2(gB[j2]);
                float2 zb = __half22float2(gB[16 + j2]);
                float2 nb = __half22float2(gB[32 + j2]);
                grB0 = rb.x; grB1 = rb.y; gzB0 = zb.x; gzB1 = zb.y; gnB0 = nb.x; gnB1 = nb.y;
            }
            h2nA[j2] = gatepair(aR0,aR1,aZ0,aZ1,aN0,aN1, br0,br1,bz0,bz1,bn0,bn1,
                                grA0,grA1,gzA0,gzA1,gnA0,gnA1, h2A[j2]);
            h2nB[j2] = gatepair(cR0,cR1,cZ0,cZ1,cN0,cN1, br0,br1,bz0,bz1,bn0,bn1,
                                grB0,grB1,gzB0,gzB1,gnB0,gnB1, h2B[j2]);
        }
        if (!FIRST) __syncwarp();   // sGi fully consumed before next stage

        if (WRITE){
            int posA = __ldg(g_pos + pA*PLEN + s);
            union { __half2 h[16]; uint4 v[4]; } mu;
            #pragma unroll
            for (int i = 0; i < 16; i++)
                mu.h[i] = __floats2half2_rn(lo2(h2nA[i]), hi2(h2nA[i]));
            uint4* mp = (uint4*)(g_msgs + (size_t)posA*HD);
            #pragma unroll
            for (int i = 0; i < 4; i++) mp[i] = mu.v[i];
            if (hasB){
                int posB = __ldg(g_pos + pB*PLEN + s);
                union { __half2 h[16]; uint4 v[4]; } mv;
                #pragma unroll
                for (int i = 0; i < 16; i++)
                    mv.h[i] = __floats2half2_rn(lo2(h2nB[i]), hi2(h2nB[i]));
                uint4* mq = (uint4*)(g_msgs + (size_t)posB*HD);
                #pragma unroll
                for (int i = 0; i < 4; i++) mq[i] = mv.v[i];
            }
        }
        #pragma unroll
        for (int i = 0; i < 16; i++){ h2A[i] = h2nA[i]; h2B[i] = h2nB[i]; }
    }

    ulonglong2* op = (ulonglong2*)(g_path_state + (size_t)pA*HD);
    #pragma unroll
    for (int i = 0; i < 8; i++){
        ulonglong2 v; v.x = h2A[2*i]; v.y = h2A[2*i+1];
        op[i] = v;
    }
    if (hasB){
        ulonglong2* oq = (ulonglong2*)(g_path_state + (size_t)pB*HD);
        #pragma unroll
        for (int i = 0; i < 8; i++){
            ulonglong2 v; v.x = h2B[2*i]; v.y = h2B[2*i+1];
            oq[i] = v;
        }
    }
}

// ---------------- link kernel: CSR segment-sum (fp16 msgs) + link GRU + next-round gi (fp16) ----------------
template<bool FIRST>
__global__ void __launch_bounds__(256) k_linkgi(const float* __restrict__ Wih,
        const float* __restrict__ Whh, const float* __restrict__ bih,
        const float* __restrict__ bhh,
        const float* __restrict__ pWih, const float* __restrict__ pbih,
        const float* __restrict__ cap)
{
    __shared__ float sWi[HD*G3];    // link Wih, transposed [k][j]
    __shared__ float sWh[HD*G3];    // link Whh, transposed [k][j]
    __shared__ float sPWT[HD*G3];   // path Wih, transposed [k][j]
    __shared__ float sbi[G3], sbh[G3], sPB[G3];
    __shared__ float sAgg[8][33], sH[8][33], sH2[8][33];
    for (int i = threadIdx.x; i < HD*G3; i += 256){
        int j = i >> 5, k = i & 31;
        sWi[k*G3 + j]  = Wih[i];
        sWh[k*G3 + j]  = Whh[i];
        sPWT[k*G3 + j] = pWih[i];
    }
    for (int i = threadIdx.x; i < G3; i += 256){
        sbi[i] = bih[i]; sbh[i] = bhh[i]; sPB[i] = pbih[i];
    }
    __syncthreads();

    int w = threadIdx.x >> 5, lane = threadIdx.x & 31;
    int l = blockIdx.x*8 + w;
    if (l >= NLINKS) return;

    if (lane == 0) g_counts[l] = 0;     // restore invariant for next kernel_launch call

    // segment sum over half2 messages: lanes 0-15 even rows, 16-31 odd rows
    int beg = g_offsets[l], end = g_offsets[l+1];
    const __half2* mb = (const __half2*)g_msgs;
    const int hl = lane & 15, rs = lane >> 4;
    float ax = 0.f, ay = 0.f, bx = 0.f, by = 0.f;
    int i = beg;
    for (; i + 4 <= end; i += 4){
        float2 f0 = __half22float2(mb[(size_t)(i +     rs)*16 + hl]);
        float2 f1 = __half22float2(mb[(size_t)(i + 2 + rs)*16 + hl]);
        ax += f0.x; ay += f0.y; bx += f1.x; by += f1.y;
    }
    for (; i + 2 <= end; i += 2){
        float2 f0 = __half22float2(mb[(size_t)(i + rs)*16 + hl]);
        ax += f0.x; ay += f0.y;
    }
    if (i < end && rs == 0){
        float2 f0 = __half22float2(mb[(size_t)i*16 + hl]);
        ax += f0.x; ay += f0.y;
    }
    ax += bx; ay += by;
    ax += __shfl_xor_sync(0xffffffffu, ax, 16);
    ay += __shfl_xor_sync(0xffffffffu, ay, 16);
    if (lane < 16){ sAgg[w][2*hl] = ax; sAgg[w][2*hl+1] = ay; }

    float hv;
    if (FIRST) hv = (lane == 0) ? __ldg(cap + l) : 0.f;   // initial link state = [cap,0..]
    else       hv = g_link_state[l*HD + lane];
    sH[w][lane] = hv;
    __syncwarp();

    int j = lane;
    float xr = sbi[j], xz = sbi[32+j], xn = sbi[64+j];
    float hr = sbh[j], hz = sbh[32+j], hnv = sbh[64+j];
    #pragma unroll
    for (int k = 0; k < HD; k++){
        float av = sAgg[w][k], hh = sH[w][k];
        xr  += av*sWi[k*G3 + j];
        xz  += av*sWi[k*G3 + 32 + j];
        xn  += av*sWi[k*G3 + 64 + j];
        hr  += hh*sWh[k*G3 + j];
        hz  += hh*sWh[k*G3 + 32 + j];
        hnv += hh*sWh[k*G3 + 64 + j];
    }
    float rr = fsig(xr + hr);
    float zz = fsig(xz + hz);
    float nn = ftanh(xn + rr*hnv);
    float hj = sH[w][j];
    float hnew = nn + zz*(hj - nn);
    g_link_state[l*HD + j] = hnew;

    // next-round path-GRU input transform: gi = hnew @ pWih^T + pbih (fp16 out)
    sH2[w][lane] = hnew;
    __syncwarp();
    float g0 = sPB[j], g1 = sPB[32+j], g2 = sPB[64+j];
    #pragma unroll
    for (int k = 0; k < HD; k++){
        float hv2 = sH2[w][k];
        g0 += hv2*sPWT[k*G3 + j];
        g1 += hv2*sPWT[k*G3 + 32 + j];
        g2 += hv2*sPWT[k*G3 + 64 + j];
    }
    g_giH[l*G3 + j]      = __float2half(g0);
    g_giH[l*G3 + 32 + j] = __float2half(g1);
    g_giH[l*G3 + 64 + j] = __float2half(g2);
}

// ---------------- readout MLP ----------------
__global__ void k_read(const float* __restrict__ W1, const float* __restrict__ b1,
                       const float* __restrict__ W2, const float* __restrict__ b2,
                       const float* __restrict__ W3, const float* __restrict__ b3,
                       float* __restrict__ out)
{
    int p = blockIdx.x*blockDim.x + threadIdx.x;
    if (p >= NPATHS) return;
    float h[HD];
    const float4* hp = (const float4*)(g_path_state + (size_t)p*HD);
    #pragma unroll
    for (int i = 0; i < 8; i++){
        float4 v = hp[i];
        h[4*i] = v.x; h[4*i+1] = v.y; h[4*i+2] = v.z; h[4*i+3] = v.w;
    }
    float x1[8];
    #pragma unroll
    for (int j = 0; j < 8; j++){
        float a = __ldg(b1 + j);
        #pragma unroll
        for (int k = 0; k < HD; k++) a += __ldg(W1 + j*HD + k) * h[k];
        x1[j] = fmaxf(a, 0.f);
    }
    float x2[8];
    #pragma unroll
    for (int j = 0; j < 8; j++){
        float a = __ldg(b2 + j);
        #pragma unroll
        for (int k = 0; k < 8; k++) a += __ldg(W2 + j*8 + k) * x1[k];
        x2[j] = fmaxf(a, 0.f);
    }
    float o = __ldg(b3);
    #pragma unroll
    for (int k = 0; k < 8; k++) o += __ldg(W3 + k) * x2[k];
    out[p] = o;
}

// ---------------- launch ----------------
extern "C" void kernel_launch(void* const* d_in, const int* in_sizes, int n_in,
                              void* d_out, int out_size)
{
    const int*   links = (const int*)  d_in[0];
    const float* cap   = (const float*)d_in[3];
    const float* bw    = (const float*)d_in[4];
    const float* pWih  = (const float*)d_in[5];
    const float* pWhh  = (const float*)d_in[6];
    const float* pbih  = (const float*)d_in[7];
    const float* pbhh  = (const float*)d_in[8];
    const float* lWih  = (const float*)d_in[9];
    const float* lWhh  = (const float*)d_in[10];
    const float* lbih  = (const float*)d_in[11];
    const float* lbhh  = (const float*)d_in[12];
    const float* W1    = (const float*)d_in[13];
    const float* b1    = (const float*)d_in[14];
    const float* W2    = (const float*)d_in[15];
    const float* b2    = (const float*)d_in[16];
    const float* W3    = (const float*)d_in[17];
    const float* b3    = (const float*)d_in[18];
    float* out = (float*)d_out;

    const int NWG = (NPATHS + 63)/64;             // 1563 warp-groups
    const int path_grid = (NWG + 1)/2;            // 782 blocks x 64 threads
    const int link_grid = (NLINKS + 7)/8;

    // launches 1-3: CSR sort of hop->link (g_counts==0 invariant on entry)
    k_hist<<<(NE + 255)/256, 256>>>(links);
    k_scan<<<1, 256>>>();
    k_pos<<<(NE + 255)/256, 256>>>(links);

    // launch 4 = round-0 k_path (the launch ncu captures)
    k_path<true,true><<<path_grid, 64>>>(links, pWhh, pbhh, pWih, pbih, cap, bw);
    k_linkgi<true><<<link_grid, 256>>>(lWih, lWhh, lbih, lbhh, pWih, pbih, cap);

    for (int t = 1; t < TROUNDS - 1; t++){
        k_path<false,true><<<path_grid, 64>>>(links, pWhh, pbhh, pWih, pbih, cap, bw);
        k_linkgi<false><<<link_grid, 256>>>(lWih, lWhh, lbih, lbhh, pWih, pbih, cap);
    }
    k_path<false,false><<<path_grid, 64>>>(links, pWhh, pbhh, pWih, pbih, cap, bw);
    k_read<<<(NPATHS + 127)/128, 128>>>(W1, b1, W2, b2, W3, b3, out);
}

// round 10
// speedup vs baseline: 1.1656x; 1.1656x over previous
#include <cuda_runtime.h>
#include <cuda_fp16.h>

#define NLINKS 10000
#define NPATHS 100000
#define PLEN 8
#define NE (NPATHS*PLEN)
#define HD 32
#define G3 96
#define TROUNDS 8
#define SROW 49   // smem gi row stride in u32 (odd -> conflict-free)

typedef unsigned long long u64;

// ---------------- scratch (device globals; no allocation allowed) ----------------
__device__ __align__(16) __half g_msgs[NE*HD];         // 51.2 MB, link-sorted hop messages (fp16)
__device__ __align__(16) float g_link_state[NLINKS*HD];
__device__ __align__(16) float g_path_state[NPATHS*HD];
__device__ __align__(16) __half g_giH[NLINKS*G3];      // per-round gi per link, fp16 (48 u32/row)
__device__ int g_counts[NLINKS];      // invariant: ==0 on kernel_launch entry (BSS init; k_linkgi restores)
__device__ int g_offsets[NLINKS+1];
__device__ int g_pos[NE];

// ---------------- helpers ----------------
__device__ __forceinline__ float fsig(float x){ return __fdividef(1.f, 1.f + __expf(-x)); }
__device__ __forceinline__ float ftanh(float x){ return __fdividef(2.f, 1.f + __expf(-2.f*x)) - 1.f; }

__device__ __forceinline__ void fma2(u64 &acc, u64 a, u64 b){
    asm("fma.rn.f32x2 %0, %1, %2, %0;" : "+l"(acc) : "l"(a), "l"(b));
}
__device__ __forceinline__ float lo2(u64 v){ return __uint_as_float((unsigned)v); }
__device__ __forceinline__ float hi2(u64 v){ return __uint_as_float((unsigned)(v>>32)); }
__device__ __forceinline__ u64 pk2(float a, float b){
    u64 r; asm("mov.b64 %0, {%1, %2};" : "=l"(r) : "f"(a), "f"(b)); return r;
}

// ---------------- setup: counting sort of links -> CSR ----------------
__global__ void k_hist(const int* __restrict__ links){
    int e = blockIdx.x*blockDim.x + threadIdx.x;
    if (e < NE) atomicAdd(&g_counts[links[e]], 1);
}
__global__ void k_scan(){
    __shared__ int ssum[256];
    const int CH = (NLINKS + 255) / 256;   // 40
    int t = threadIdx.x;
    int base = t*CH;
    int s = 0;
    for (int i = 0; i < CH; i++){ int x = base+i; if (x < NLINKS) s += g_counts[x]; }
    ssum[t] = s;
    __syncthreads();
    if (t == 0){
        int run = 0;
        for (int i = 0; i < 256; i++){ int v = ssum[i]; ssum[i] = run; run += v; }
        g_offsets[NLINKS] = run;
    }
    __syncthreads();
    int run = ssum[t];
    for (int i = 0; i < CH; i++){
        int x = base+i;
        if (x < NLINKS){ g_offsets[x] = run; run += g_counts[x]; g_counts[x] = 0; }
    }
}
__global__ void k_pos(const int* __restrict__ links){
    int e = blockIdx.x*blockDim.x + threadIdx.x;
    if (e < NE){
        int l = links[e];
        g_pos[e] = g_offsets[l] + atomicAdd(&g_counts[l], 1);
    }
}

// ---------------- path GRU: 8 steps, 1 path/thread, f32x2 FMAs, occ-4 ----------------
// FIRST: round 0 — h init = [bw,0..], gi inline from cap (no staging).
// WRITE: write per-hop messages (skipped last round).
template<bool FIRST, bool WRITE>
__global__ void __launch_bounds__(128, 4) k_path(const int* __restrict__ links,
        const float* __restrict__ pWhh, const float* __restrict__ pbhh,
        const float* __restrict__ pWih, const float* __restrict__ pbih,
        const float* __restrict__ cap, const float* __restrict__ bw)
{
    __shared__ __align__(16) float sW[G3*HD];   // Whh row-major [96][32]
    __shared__ float sb[G3];                    // bhh
    __shared__ float sW0[G3], sB0[G3];          // round-0 inline gi: Wih col0 + bih
    __shared__ unsigned sGiU[4][32*SROW];       // fp16 staged gi rows per warp (48 u32 payload + pad)

    for (int i = threadIdx.x; i < G3*HD; i += 128) sW[i] = pWhh[i];
    for (int i = threadIdx.x; i < G3;    i += 128){
        sb[i] = pbhh[i];
        if (FIRST){ sW0[i] = pWih[i*HD]; sB0[i] = pbih[i]; }
    }
    __syncthreads();

    const int w = threadIdx.x >> 5, lane = threadIdx.x & 31;
    const int wg = blockIdx.x*4 + w;
    if (wg >= NPATHS/32) return;                 // warp-uniform (NPATHS % 32 == 0)
    const int p = wg*32 + lane;

    u64 h2[16], h2n[16];
    if (FIRST){
        h2[0] = pk2(__ldg(bw + p), 0.f);
        #pragma unroll
        for (int i = 1; i < 16; i++) h2[i] = 0ull;
    } else {
        const float4* hp = (const float4*)(g_path_state + (size_t)p*HD);
        #pragma unroll
        for (int i = 0; i < 8; i++){
            float4 v = hp[i];
            h2[2*i] = pk2(v.x, v.y); h2[2*i+1] = pk2(v.z, v.w);
        }
    }

    unsigned* myGiU = &sGiU[w][0];
    const __half2* gA = (const __half2*)(myGiU + lane*SROW);

    #pragma unroll 1
    for (int s = 0; s < PLEN; s++){
        int lnk = __ldg(links + p*PLEN + s);
        float mycap = 0.f;
        if (FIRST){
            mycap = __ldg(cap + lnk);
        } else {
            // stage this warp's 32 gi rows (48 u32 of fp16 each), coalesced
            const unsigned* gbase = (const unsigned*)g_giH;
            #pragma unroll
            for (int r = 0; r < 32; r++){
                int lr = __shfl_sync(0xffffffffu, lnk, r);
                const unsigned* g = gbase + lr*48;
                unsigned* dst = myGiU + r*SROW;
                dst[lane] = g[lane];
                if (lane < 16) dst[32 + lane] = g[32 + lane];
            }
            __syncwarp();
        }

        #pragma unroll
        for (int j2 = 0; j2 < 16; j2++){
            const int j0 = 2*j2, j1 = j0 + 1;
            u64 aR0=0ull,aR1=0ull,aZ0=0ull,aZ1=0ull,aN0=0ull,aN1=0ull;
            const ulonglong2* wR0 = (const ulonglong2*)(sW + j0*HD);
            const ulonglong2* wR1 = (const ulonglong2*)(sW + j1*HD);
            const ulonglong2* wZ0 = (const ulonglong2*)(sW + (32+j0)*HD);
            const ulonglong2* wZ1 = (const ulonglong2*)(sW + (32+j1)*HD);
            const ulonglong2* wN0 = (const ulonglong2*)(sW + (64+j0)*HD);
            const ulonglong2* wN1 = (const ulonglong2*)(sW + (64+j1)*HD);
            #pragma unroll
            for (int k = 0; k < 8; k++){
                u64 ha = h2[2*k], hb = h2[2*k+1];
                ulonglong2 a = wR0[k]; fma2(aR0, ha, a.x); fma2(aR0, hb, a.y);
                ulonglong2 b = wR1[k]; fma2(aR1, ha, b.x); fma2(aR1, hb, b.y);
                ulonglong2 c = wZ0[k]; fma2(aZ0, ha, c.x); fma2(aZ0, hb, c.y);
                ulonglong2 d = wZ1[k]; fma2(aZ1, ha, d.x); fma2(aZ1, hb, d.y);
                ulonglong2 e = wN0[k]; fma2(aN0, ha, e.x); fma2(aN0, hb, e.y);
                ulonglong2 f = wN1[k]; fma2(aN1, ha, f.x); fma2(aN1, hb, f.y);
            }
            float ghr0 = lo2(aR0) + hi2(aR0) + sb[j0];
            float ghr1 = lo2(aR1) + hi2(aR1) + sb[j1];
            float ghz0 = lo2(aZ0) + hi2(aZ0) + sb[32+j0];
            float ghz1 = lo2(aZ1) + hi2(aZ1) + sb[32+j1];
            float ghn0 = lo2(aN0) + hi2(aN0) + sb[64+j0];
            float ghn1 = lo2(aN1) + hi2(aN1) + sb[64+j1];
            float gr0, gr1, gz0, gz1, gn0, gn1;
            if (FIRST){
                gr0 = __fmaf_rn(mycap, sW0[j0], sB0[j0]);
                gr1 = __fmaf_rn(mycap, sW0[j1], sB0[j1]);
                gz0 = __fmaf_rn(mycap, sW0[32+j0], sB0[32+j0]);
                gz1 = __fmaf_rn(mycap, sW0[32+j1], sB0[32+j1]);
                gn0 = __fmaf_rn(mycap, sW0[64+j0], sB0[64+j0]);
                gn1 = __fmaf_rn(mycap, sW0[64+j1], sB0[64+j1]);
            } else {
                float2 r = __half22float2(gA[j2]);
                float2 z = __half22float2(gA[16 + j2]);
                float2 n = __half22float2(gA[32 + j2]);
                gr0 = r.x; gr1 = r.y; gz0 = z.x; gz1 = z.y; gn0 = n.x; gn1 = n.y;
            }
            float r0 = fsig(gr0 + ghr0), r1 = fsig(gr1 + ghr1);
            float z0 = fsig(gz0 + ghz0), z1 = fsig(gz1 + ghz1);
            float n0 = ftanh(gn0 + r0*ghn0), n1 = ftanh(gn1 + r1*ghn1);
            float h0 = lo2(h2[j2]), h1 = hi2(h2[j2]);
            h2n[j2] = pk2(n0 + z0*(h0 - n0), n1 + z1*(h1 - n1));
        }
        if (!FIRST) __syncwarp();   // sGi fully consumed before next stage

        if (WRITE){
            int pos = __ldg(g_pos + p*PLEN + s);
            union { __half2 h[16]; uint4 v[4]; } mu;
            #pragma unroll
            for (int i = 0; i < 16; i++)
                mu.h[i] = __floats2half2_rn(lo2(h2n[i]), hi2(h2n[i]));
            uint4* mp = (uint4*)(g_msgs + (size_t)pos*HD);
            #pragma unroll
            for (int i = 0; i < 4; i++) mp[i] = mu.v[i];
        }
        #pragma unroll
        for (int i = 0; i < 16; i++) h2[i] = h2n[i];
    }

    ulonglong2* op = (ulonglong2*)(g_path_state + (size_t)p*HD);
    #pragma unroll
    for (int i = 0; i < 8; i++){
        ulonglong2 v; v.x = h2[2*i]; v.y = h2[2*i+1];
        op[i] = v;
    }
}

// ---------------- link kernel: CSR segment-sum (uint4 loads) + link GRU + next-round gi ----------------
template<bool FIRST>
__global__ void __launch_bounds__(256) k_linkgi(const float* __restrict__ Wih,
        const float* __restrict__ Whh, const float* __restrict__ bih,
        const float* __restrict__ bhh,
        const float* __restrict__ pWih, const float* __restrict__ pbih,
        const float* __restrict__ cap)
{
    __shared__ float sWi[HD*G3];    // link Wih, transposed [k][j]
    __shared__ float sWh[HD*G3];    // link Whh, transposed [k][j]
    __shared__ float sPWT[HD*G3];   // path Wih, transposed [k][j]
    __shared__ float sbi[G3], sbh[G3], sPB[G3];
    __shared__ float sAgg[8][33], sH[8][33], sH2[8][33];
    for (int i = threadIdx.x; i < HD*G3; i += 256){
        int j = i >> 5, k = i & 31;
        sWi[k*G3 + j]  = Wih[i];
        sWh[k*G3 + j]  = Whh[i];
        sPWT[k*G3 + j] = pWih[i];
    }
    for (int i = threadIdx.x; i < G3; i += 256){
        sbi[i] = bih[i]; sbh[i] = bhh[i]; sPB[i] = pbih[i];
    }
    __syncthreads();

    int w = threadIdx.x >> 5, lane = threadIdx.x & 31;
    int l = blockIdx.x*8 + w;
    if (l >= NLINKS) return;

    if (lane == 0) g_counts[l] = 0;     // restore invariant for next kernel_launch call

    // segment sum: lane = (r,q); r=lane>>2 row-offset (8 rows/iter), q=lane&3 -> 8 features
    {
        int beg = g_offsets[l], end = g_offsets[l+1];
        const int r = lane >> 2, q = lane & 3;
        float acc[8];
        #pragma unroll
        for (int t = 0; t < 8; t++) acc[t] = 0.f;
        for (int i = beg; i < end; i += 8){
            int row = i + r;
            if (row < end){
                uint4 v = *(const uint4*)(g_msgs + (size_t)row*HD + q*8);
                const __half2* hp = (const __half2*)&v;
                #pragma unroll
                for (int t = 0; t < 4; t++){
                    float2 f = __half22float2(hp[t]);
                    acc[2*t]   += f.x;
                    acc[2*t+1] += f.y;
                }
            }
        }
        #pragma unroll
        for (int d = 4; d <= 16; d <<= 1){
            #pragma unroll
            for (int t = 0; t < 8; t++)
                acc[t] += __shfl_xor_sync(0xffffffffu, acc[t], d);
        }
        if (lane < 4){
            #pragma unroll
            for (int t = 0; t < 8; t++) sAgg[w][q*8 + t] = acc[t];
        }
    }

    float hv;
    if (FIRST) hv = (lane == 0) ? __ldg(cap + l) : 0.f;   // initial link state = [cap,0..]
    else       hv = g_link_state[l*HD + lane];
    sH[w][lane] = hv;
    __syncwarp();

    int j = lane;
    float xr = sbi[j], xz = sbi[32+j], xn = sbi[64+j];
    float hr = sbh[j], hz = sbh[32+j], hnv = sbh[64+j];
    #pragma unroll
    for (int k = 0; k < HD; k++){
        float av = sAgg[w][k], hh = sH[w][k];
        xr  += av*sWi[k*G3 + j];
        xz  += av*sWi[k*G3 + 32 + j];
        xn  += av*sWi[k*G3 + 64 + j];
        hr  += hh*sWh[k*G3 + j];
        hz  += hh*sWh[k*G3 + 32 + j];
        hnv += hh*sWh[k*G3 + 64 + j];
    }
    float rr = fsig(xr + hr);
    float zz = fsig(xz + hz);
    float nn = ftanh(xn + rr*hnv);
    float hj = sH[w][j];
    float hnew = nn + zz*(hj - nn);
    g_link_state[l*HD + j] = hnew;

    // next-round path-GRU input transform: gi = hnew @ pWih^T + pbih (fp16 out)
    sH2[w][lane] = hnew;
    __syncwarp();
    float g0 = sPB[j], g1 = sPB[32+j], g2 = sPB[64+j];
    #pragma unroll
    for (int k = 0; k < HD; k++){
        float hv2 = sH2[w][k];
        g0 += hv2*sPWT[k*G3 + j];
        g1 += hv2*sPWT[k*G3 + 32 + j];
        g2 += hv2*sPWT[k*G3 + 64 + j];
    }
    g_giH[l*G3 + j]      = __float2half(g0);
    g_giH[l*G3 + 32 + j] = __float2half(g1);
    g_giH[l*G3 + 64 + j] = __float2half(g2);
}

// ---------------- readout MLP ----------------
__global__ void k_read(const float* __restrict__ W1, const float* __restrict__ b1,
                       const float* __restrict__ W2, const float* __restrict__ b2,
                       const float* __restrict__ W3, const float* __restrict__ b3,
                       float* __restrict__ out)
{
    int p = blockIdx.x*blockDim.x + threadIdx.x;
    if (p >= NPATHS) return;
    float h[HD];
    const float4* hp = (const float4*)(g_path_state + (size_t)p*HD);
    #pragma unroll
    for (int i = 0; i < 8; i++){
        float4 v = hp[i];
        h[4*i] = v.x; h[4*i+1] = v.y; h[4*i+2] = v.z; h[4*i+3] = v.w;
    }
    float x1[8];
    #pragma unroll
    for (int j = 0; j < 8; j++){
        float a = __ldg(b1 + j);
        #pragma unroll
        for (int k = 0; k < HD; k++) a += __ldg(W1 + j*HD + k) * h[k];
        x1[j] = fmaxf(a, 0.f);
    }
    float x2[8];
    #pragma unroll
    for (int j = 0; j < 8; j++){
        float a = __ldg(b2 + j);
        #pragma unroll
        for (int k = 0; k < 8; k++) a += __ldg(W2 + j*8 + k) * x1[k];
        x2[j] = fmaxf(a, 0.f);
    }
    float o = __ldg(b3);
    #pragma unroll
    for (int k = 0; k < 8; k++) o += __ldg(W3 + k) * x2[k];
    out[p] = o;
}

// ---------------- launch ----------------
extern "C" void kernel_launch(void* const* d_in, const int* in_sizes, int n_in,
                              void* d_out, int out_size)
{
    const int*   links = (const int*)  d_in[0];
    const float* cap   = (const float*)d_in[3];
    const float* bw    = (const float*)d_in[4];
    const float* pWih  = (const float*)d_in[5];
    const float* pWhh  = (const float*)d_in[6];
    const float* pbih  = (const float*)d_in[7];
    const float* pbhh  = (const float*)d_in[8];
    const float* lWih  = (const float*)d_in[9];
    const float* lWhh  = (const float*)d_in[10];
    const float* lbih  = (const float*)d_in[11];
    const float* lbhh  = (const float*)d_in[12];
    const float* W1    = (const float*)d_in[13];
    const float* b1    = (const float*)d_in[14];
    const float* W2    = (const float*)d_in[15];
    const float* b2    = (const float*)d_in[16];
    const float* W3    = (const float*)d_in[17];
    const float* b3    = (const float*)d_in[18];
    float* out = (float*)d_out;

    const int nwarps = NPATHS/32;                 // 3125
    const int path_grid = (nwarps + 3)/4;         // 782 blocks x 128 threads
    const int link_grid = (NLINKS + 7)/8;

    // launches 1-3: CSR sort of hop->link (g_counts==0 invariant on entry)
    k_hist<<<(NE + 255)/256, 256>>>(links);
    k_scan<<<1, 256>>>();
    k_pos<<<(NE + 255)/256, 256>>>(links);

    // launch 4 = round-0 k_path (the launch ncu captures)
    k_path<true,true><<<path_grid, 128>>>(links, pWhh, pbhh, pWih, pbih, cap, bw);
    k_linkgi<true><<<link_grid, 256>>>(lWih, lWhh, lbih, lbhh, pWih, pbih, cap);

    for (int t = 1; t < TROUNDS - 1; t++){
        k_path<false,true><<<path_grid, 128>>>(links, pWhh, pbhh, pWih, pbih, cap, bw);
        k_linkgi<false><<<link_grid, 256>>>(lWih, lWhh, lbih, lbhh, pWih, pbih, cap);
    }
    k_path<false,false><<<path_grid, 128>>>(links, pWhh, pbhh, pWih, pbih, cap, bw);
    k_read<<<(NPATHS + 127)/128, 128>>>(W1, b1, W2, b2, W3, b3, out);
}